// round 3
// baseline (speedup 1.0000x reference)
#include <cuda_runtime.h>
#include <cuda_bf16.h>
#include <cstdint>

// ---------------------------------------------------------------------------
// Shapes: T=S=512, B=64, D=512, H=5, QHD=32, PHD=4, PD=192
// ---------------------------------------------------------------------------

static __device__ float g_lm[32768 * 180];   // projected lm (q | p)
static __device__ float g_k [32768 * 160];   // projected am (k)
static __device__ float g_pe[1023 * 20];     // projected pos emb

__device__ __forceinline__ uint32_t sptr(const void* p) {
    return (uint32_t)__cvta_generic_to_shared(p);
}
__device__ __forceinline__ void ldsm_x4(uint32_t addr, uint32_t& r0, uint32_t& r1,
                                        uint32_t& r2, uint32_t& r3) {
    asm volatile("ldmatrix.sync.aligned.m8n8.x4.shared.b16 {%0,%1,%2,%3}, [%4];"
                 : "=r"(r0), "=r"(r1), "=r"(r2), "=r"(r3) : "r"(addr));
}
__device__ __forceinline__ void mma_bf16(float* c, const uint32_t* a, uint32_t b0, uint32_t b1) {
    asm volatile("mma.sync.aligned.m16n8k16.row.col.f32.bf16.bf16.f32 "
                 "{%0,%1,%2,%3},{%4,%5,%6,%7},{%8,%9},{%0,%1,%2,%3};"
                 : "+f"(c[0]), "+f"(c[1]), "+f"(c[2]), "+f"(c[3])
                 : "r"(a[0]), "r"(a[1]), "r"(a[2]), "r"(a[3]), "r"(b0), "r"(b1));
}
__device__ __forceinline__ void split_bf16(float x, __nv_bfloat16& h, __nv_bfloat16& l) {
    h = __float2bfloat16(x);
    l = __float2bfloat16(x - __bfloat162float(h));
}

// ---------------------------------------------------------------------------
// Projection GEMM on tensor cores: C[32768, N] = X[32768,512] @ W[512,N] + b
// Split-bf16 (3-term): err ~1e-5. BM=128, BN=64, BK=32, 8 warps (4m x 2n).
// ---------------------------------------------------------------------------
#define AK 40   // padded K stride (elements) -> 80B rows, conflict-free ldmatrix

__global__ __launch_bounds__(256)
void proj_mma_kernel(const float* __restrict__ X, const float* __restrict__ W,
                     const float* __restrict__ bias, float* __restrict__ C,
                     const int N)
{
    __shared__ __nv_bfloat16 Ah[128 * AK], Al[128 * AK];
    __shared__ __nv_bfloat16 Bh[64 * AK],  Bl[64 * AK];

    const int tid = threadIdx.x;
    const int m0 = blockIdx.x * 128;
    const int n0 = blockIdx.y * 64;
    const int w = tid >> 5, lane = tid & 31;
    const int wm = (w >> 1) * 32;      // warp m offset in tile
    const int wn = (w & 1) * 32;       // warp n offset in tile

    float acc[2][4][4];
#pragma unroll
    for (int mt = 0; mt < 2; ++mt)
#pragma unroll
        for (int nt = 0; nt < 4; ++nt)
#pragma unroll
            for (int c = 0; c < 4; ++c) acc[mt][nt][c] = 0.f;

    for (int kt = 0; kt < 512; kt += 32) {
        // ---- A tile 128x32 fp32 -> split bf16 (hi/lo)
#pragma unroll
        for (int s = 0; s < 4; ++s) {
            const int f = tid + 256 * s;             // 0..1023
            const int row = f >> 3;
            const int c4 = (f & 7) * 4;
            const float4 v = *(const float4*)&X[(size_t)(m0 + row) * 512 + kt + c4];
            __nv_bfloat16 h0, l0, h1, l1, h2, l2, h3, l3;
            split_bf16(v.x, h0, l0); split_bf16(v.y, h1, l1);
            split_bf16(v.z, h2, l2); split_bf16(v.w, h3, l3);
            *(ushort4*)&Ah[row * AK + c4] = make_ushort4(
                __bfloat16_as_ushort(h0), __bfloat16_as_ushort(h1),
                __bfloat16_as_ushort(h2), __bfloat16_as_ushort(h3));
            *(ushort4*)&Al[row * AK + c4] = make_ushort4(
                __bfloat16_as_ushort(l0), __bfloat16_as_ushort(l1),
                __bfloat16_as_ushort(l2), __bfloat16_as_ushort(l3));
        }
        // ---- B tile 32(k) x 64(n), stored transposed Bs[n][k]
#pragma unroll
        for (int s = 0; s < 8; ++s) {
            const int f = tid + 256 * s;             // 0..2047
            const int k = f >> 6;
            const int n = f & 63;
            const float wv = (n0 + n < N) ? W[(size_t)(kt + k) * N + n0 + n] : 0.f;
            __nv_bfloat16 h, l;
            split_bf16(wv, h, l);
            Bh[n * AK + k] = h;
            Bl[n * AK + k] = l;
        }
        __syncthreads();

#pragma unroll
        for (int ks = 0; ks < 2; ++ks) {
            uint32_t ah[2][4], al[2][4], bh[2][4], bl[2][4];
#pragma unroll
            for (int mt = 0; mt < 2; ++mt) {
                const int roff = (wm + mt * 16 + (lane & 15)) * AK + ks * 16 + ((lane >> 4) & 1) * 8;
                ldsm_x4(sptr(&Ah[roff]), ah[mt][0], ah[mt][1], ah[mt][2], ah[mt][3]);
                ldsm_x4(sptr(&Al[roff]), al[mt][0], al[mt][1], al[mt][2], al[mt][3]);
            }
#pragma unroll
            for (int ntp = 0; ntp < 2; ++ntp) {
                const int roff = (wn + ntp * 16 + (lane & 7) + ((lane >> 4) & 1) * 8) * AK
                               + ks * 16 + ((lane >> 3) & 1) * 8;
                ldsm_x4(sptr(&Bh[roff]), bh[ntp][0], bh[ntp][1], bh[ntp][2], bh[ntp][3]);
                ldsm_x4(sptr(&Bl[roff]), bl[ntp][0], bl[ntp][1], bl[ntp][2], bl[ntp][3]);
            }
#pragma unroll
            for (int mt = 0; mt < 2; ++mt)
#pragma unroll
                for (int nt = 0; nt < 4; ++nt) {
                    const int p = nt >> 1, q = (nt & 1) * 2;
                    mma_bf16(acc[mt][nt], al[mt], bh[p][q], bh[p][q + 1]);
                    mma_bf16(acc[mt][nt], ah[mt], bl[p][q], bl[p][q + 1]);
                    mma_bf16(acc[mt][nt], ah[mt], bh[p][q], bh[p][q + 1]);
                }
        }
        __syncthreads();
    }

    // ---- epilogue: c0,c1=(r, col..col+1), c2,c3=(r+8, ...)
#pragma unroll
    for (int mt = 0; mt < 2; ++mt) {
        const int r = m0 + wm + mt * 16 + (lane >> 2);
#pragma unroll
        for (int nt = 0; nt < 4; ++nt) {
            const int col = n0 + wn + nt * 8 + (lane & 3) * 2;
            if (col < N) {
                const float2 bb = *(const float2*)&bias[col];
                float2 o0, o1;
                o0.x = acc[mt][nt][0] + bb.x;  o0.y = acc[mt][nt][1] + bb.y;
                o1.x = acc[mt][nt][2] + bb.x;  o1.y = acc[mt][nt][3] + bb.y;
                *(float2*)&C[(size_t)r * N + col] = o0;
                *(float2*)&C[(size_t)(r + 8) * N + col] = o1;
            }
        }
    }
}

// ---------------------------------------------------------------------------
// pe projection: (1023,192) @ (192,20)
// ---------------------------------------------------------------------------
__global__ __launch_bounds__(256)
void pe_proj_kernel(const float* __restrict__ pos, const float* __restrict__ Wp,
                    float* __restrict__ outp)
{
    const int idx = blockIdx.x * 256 + threadIdx.x;
    if (idx >= 1023 * 20) return;
    const int n = idx / 20;
    const int c = idx % 20;
    float s = 0.f;
#pragma unroll 8
    for (int d = 0; d < 192; ++d)
        s = fmaf(pos[n * 192 + d], Wp[d * 20 + c], s);
    outp[idx] = s;
}

// ---------------------------------------------------------------------------
// Fused attention weights. Block = 32 t-rows x 512 keys for one (b,h).
// 8 warps = 4 row-groups (8 rows each) x 2 col-halves (256 cols each).
// acc[8][8] per thread; cross-warp softmax combine via tiny static smem.
// ---------------------------------------------------------------------------
__global__ __launch_bounds__(256, 2)
void attn_kernel(const float* __restrict__ lmP, const float* __restrict__ kP,
                 const float* __restrict__ peP, const unsigned char* __restrict__ mask,
                 float* __restrict__ out)
{
    extern __shared__ float smem[];
    float* ks = smem;                               // [32 d][512 j]
    float* qs = ks + 32 * 512;                      // [32 d][32 r]
    float4* pes = (float4*)(qs + 32 * 32);          // [544]
    float4* ps  = pes + 544;                        // [32]
    unsigned char* msk = (unsigned char*)(ps + 32); // [512]
    __shared__ float redmax[4][8][2];
    __shared__ float redsum[4][8][2];

    const int t0 = blockIdx.x * 32;
    const int b  = blockIdx.y;
    const int h  = blockIdx.z;
    const int tid = threadIdx.x;

    // ---- K tile transpose 512x32 -> ks[d][j]
#pragma unroll
    for (int s = 0; s < 16; ++s) {
        const int it = tid + 256 * s;               // 0..4095
        const int d4 = it >> 9;
        const int j  = it & 511;
        const float4 v = *(const float4*)&kP[((size_t)j * 64 + b) * 160 + h * 32 + d4 * 4];
        ks[(d4 * 4 + 0) * 512 + j] = v.x;
        ks[(d4 * 4 + 1) * 512 + j] = v.y;
        ks[(d4 * 4 + 2) * 512 + j] = v.z;
        ks[(d4 * 4 + 3) * 512 + j] = v.w;
    }
    // ---- Q tile 32x32 -> qs[d][r]
    {
        const int d4 = tid >> 5;
        const int r  = tid & 31;
        const float4 v = *(const float4*)&lmP[((size_t)(t0 + r) * 64 + b) * 180 + h * 32 + d4 * 4];
        qs[(d4 * 4 + 0) * 32 + r] = v.x;
        qs[(d4 * 4 + 1) * 32 + r] = v.y;
        qs[(d4 * 4 + 2) * 32 + r] = v.z;
        qs[(d4 * 4 + 3) * 32 + r] = v.w;
    }
    if (tid < 32)
        ps[tid] = *(const float4*)&lmP[((size_t)(t0 + tid) * 64 + b) * 180 + 160 + h * 4];
    for (int it = tid; it < 543; it += 256) {
        const int n = 480 - t0 + it;                // always in [0,1023)
        pes[it] = *(const float4*)&peP[n * 20 + h * 4];
    }
    for (int it = tid; it < 512; it += 256) msk[it] = mask[b * 512 + it];
    __syncthreads();

    const int w = tid >> 5, lane = tid & 31;
    const int wy = w >> 1;                          // row group 0..3
    const int wx = w & 1;                           // col half 0..1

    const float4* ks4 = (const float4*)ks;          // [32][128]
    const float4* qs4 = (const float4*)qs;          // [32][8]

    float acc[8][8];
#pragma unroll
    for (int i = 0; i < 8; ++i)
#pragma unroll
        for (int j = 0; j < 8; ++j) acc[i][j] = 0.f;

    // ---- content scores: 1 kv LDS.128 + 2 broadcast LDS.128 per 32 FMA
#pragma unroll
    for (int cp = 0; cp < 2; ++cp) {
#pragma unroll 4
        for (int d = 0; d < 32; ++d) {
            const float4 kv = ks4[d * 128 + wx * 64 + cp * 32 + lane];
            const float4 q0 = qs4[d * 8 + wy * 2];
            const float4 q1 = qs4[d * 8 + wy * 2 + 1];
            const float qa[8] = {q0.x, q0.y, q0.z, q0.w, q1.x, q1.y, q1.z, q1.w};
            const float ka[4] = {kv.x, kv.y, kv.z, kv.w};
#pragma unroll
            for (int i = 0; i < 8; ++i)
#pragma unroll
                for (int c = 0; c < 4; ++c)
                    acc[i][cp * 4 + c] = fmaf(qa[i], ka[c], acc[i][cp * 4 + c]);
        }
    }

    // ---- positional scores: n_local = col + 31 - row_local, in [0,542]
#pragma unroll
    for (int i = 0; i < 8; ++i) {
        const int rl = wy * 8 + i;
        const float4 pv = ps[rl];
#pragma unroll
        for (int cp = 0; cp < 2; ++cp)
#pragma unroll
            for (int c = 0; c < 4; ++c) {
                const int col = wx * 256 + cp * 128 + lane * 4 + c;
                const float4 ev = pes[col + 31 - rl];
                acc[i][cp * 4 + c] += pv.x * ev.x + pv.y * ev.y + pv.z * ev.z + pv.w * ev.w;
            }
    }

    // ---- mask
#pragma unroll
    for (int i = 0; i < 8; ++i)
#pragma unroll
        for (int j = 0; j < 8; ++j) {
            const int col = wx * 256 + (j >> 2) * 128 + lane * 4 + (j & 3);
            if (msk[col]) acc[i][j] = -1000.f;
        }

    // ---- softmax: warp-local max -> cross-warp combine -> exp/sum -> combine
#pragma unroll
    for (int i = 0; i < 8; ++i) {
        float m = acc[i][0];
#pragma unroll
        for (int j = 1; j < 8; ++j) m = fmaxf(m, acc[i][j]);
#pragma unroll
        for (int off = 16; off > 0; off >>= 1)
            m = fmaxf(m, __shfl_xor_sync(0xffffffffu, m, off));
        if (lane == 0) redmax[wy][i][wx] = m;
    }
    __syncthreads();
#pragma unroll
    for (int i = 0; i < 8; ++i) {
        const float gm = fmaxf(redmax[wy][i][0], redmax[wy][i][1]);
        float s = 0.f;
#pragma unroll
        for (int j = 0; j < 8; ++j) {
            acc[i][j] = __expf(acc[i][j] - gm);
            s += acc[i][j];
        }
#pragma unroll
        for (int off = 16; off > 0; off >>= 1)
            s += __shfl_xor_sync(0xffffffffu, s, off);
        if (lane == 0) redsum[wy][i][wx] = s;
    }
    __syncthreads();
#pragma unroll
    for (int i = 0; i < 8; ++i) {
        const float inv = 1.f / (redsum[wy][i][0] + redsum[wy][i][1]);
        const int rg = t0 + wy * 8 + i;
        const size_t base = (((size_t)h * 64 + b) * 512 + rg) * 512;
#pragma unroll
        for (int cp = 0; cp < 2; ++cp) {
            float4 o;
            o.x = acc[i][cp * 4 + 0] * inv;
            o.y = acc[i][cp * 4 + 1] * inv;
            o.z = acc[i][cp * 4 + 2] * inv;
            o.w = acc[i][cp * 4 + 3] * inv;
            *(float4*)&out[base + wx * 256 + cp * 128 + lane * 4] = o;
        }
    }
}

// ---------------------------------------------------------------------------
extern "C" void kernel_launch(void* const* d_in, const int* in_sizes, int n_in,
                              void* d_out, int out_size)
{
    const float* lm_pruned = (const float*)d_in[0];
    const float* am_pruned = (const float*)d_in[1];
    const float* pos_emb   = (const float*)d_in[2];
    const unsigned char* kpm = (const unsigned char*)d_in[3];
    const float* W_lm  = (const float*)d_in[4];
    const float* b_lm  = (const float*)d_in[5];
    const float* W_am  = (const float*)d_in[6];
    const float* b_am  = (const float*)d_in[7];
    const float* W_pos = (const float*)d_in[8];
    float* out = (float*)d_out;

    float *p_lm, *p_k, *p_pe;
    cudaGetSymbolAddress((void**)&p_lm, g_lm);
    cudaGetSymbolAddress((void**)&p_k,  g_k);
    cudaGetSymbolAddress((void**)&p_pe, g_pe);

    proj_mma_kernel<<<dim3(256, 3), 256>>>(lm_pruned, W_lm, b_lm, p_lm, 180);
    proj_mma_kernel<<<dim3(256, 3), 256>>>(am_pruned, W_am, b_am, p_k, 160);
    pe_proj_kernel<<<80, 256>>>(pos_emb, W_pos, p_pe);

    const int smem_bytes = (32 * 512 + 32 * 32) * 4 + 544 * 16 + 32 * 16 + 512; // 79360
    cudaFuncSetAttribute(attn_kernel, cudaFuncAttributeMaxDynamicSharedMemorySize, smem_bytes);
    attn_kernel<<<dim3(16, 64, 5), 256, smem_bytes>>>(p_lm, p_k, p_pe, kpm, out);
}

// round 5
// speedup vs baseline: 2.1233x; 2.1233x over previous
#include <cuda_runtime.h>
#include <cuda_bf16.h>
#include <cstdint>

// ---------------------------------------------------------------------------
// Shapes: T=S=512, B=64, D=512, H=5, QHD=32, PHD=4, PD=192
// Pre-split bf16 hi/lo intermediates in [b][t][col] layout for attn loads.
// ---------------------------------------------------------------------------
static __device__ __nv_bfloat16 g_qh[64 * 512 * 160];
static __device__ __nv_bfloat16 g_ql[64 * 512 * 160];
static __device__ __nv_bfloat16 g_kh[64 * 512 * 160];
static __device__ __nv_bfloat16 g_kl[64 * 512 * 160];
static __device__ float        g_p [64 * 512 * 20];
static __device__ float        g_pe[1023 * 20];

__device__ __forceinline__ uint32_t sptr(const void* p) {
    return (uint32_t)__cvta_generic_to_shared(p);
}
__device__ __forceinline__ void ldsm_x4(uint32_t a, uint32_t& r0, uint32_t& r1,
                                        uint32_t& r2, uint32_t& r3) {
    asm volatile("ldmatrix.sync.aligned.m8n8.x4.shared.b16 {%0,%1,%2,%3}, [%4];"
                 : "=r"(r0), "=r"(r1), "=r"(r2), "=r"(r3) : "r"(a));
}
__device__ __forceinline__ void ldsm_x4_t(uint32_t a, uint32_t& r0, uint32_t& r1,
                                          uint32_t& r2, uint32_t& r3) {
    asm volatile("ldmatrix.sync.aligned.m8n8.x4.trans.shared.b16 {%0,%1,%2,%3}, [%4];"
                 : "=r"(r0), "=r"(r1), "=r"(r2), "=r"(r3) : "r"(a));
}
__device__ __forceinline__ void mma_bf16(float* c, const uint32_t* a, uint32_t b0, uint32_t b1) {
    asm volatile("mma.sync.aligned.m16n8k16.row.col.f32.bf16.bf16.f32 "
                 "{%0,%1,%2,%3},{%4,%5,%6,%7},{%8,%9},{%0,%1,%2,%3};"
                 : "+f"(c[0]), "+f"(c[1]), "+f"(c[2]), "+f"(c[3])
                 : "r"(a[0]), "r"(a[1]), "r"(a[2]), "r"(a[3]), "r"(b0), "r"(b1));
}
__device__ __forceinline__ void split_bf16(float x, __nv_bfloat16& h, __nv_bfloat16& l) {
    h = __float2bfloat16(x);
    l = __float2bfloat16(x - __bfloat162float(h));
}
__device__ __forceinline__ ushort2 pack_hi2(float a, float b) {
    __nv_bfloat16 ha, la, hb, lb;
    split_bf16(a, ha, la); split_bf16(b, hb, lb);
    return make_ushort2(__bfloat16_as_ushort(ha), __bfloat16_as_ushort(hb));
}
__device__ __forceinline__ ushort2 pack_lo2(float a, float b) {
    __nv_bfloat16 ha, la, hb, lb;
    split_bf16(a, ha, la); split_bf16(b, hb, lb);
    return make_ushort2(__bfloat16_as_ushort(la), __bfloat16_as_ushort(lb));
}

// ---------------------------------------------------------------------------
// Projection GEMM v2.  C[32768, N] = X @ W + b, written pre-split to globals.
// BM=128, BN=192 (single n-block!), BK=32, double-buffered, 8 warps (4m x 2n).
// B stored [k][n] and consumed via ldmatrix.trans.  mode 0 = am->k, 1 = lm->q|p.
// ---------------------------------------------------------------------------
#define PA 40    // A row pad (bf16)
#define PB 200   // B row pad (bf16)
#define ASZ (128 * PA)
#define BSZ (32 * PB)

__global__ __launch_bounds__(256)
void proj_mma2(const float* __restrict__ X, const float* __restrict__ W,
               const float* __restrict__ bias, const int N, const int mode)
{
    extern __shared__ char sm[];
    __nv_bfloat16* Ah = (__nv_bfloat16*)sm;          // [2][ASZ]
    __nv_bfloat16* Al = Ah + 2 * ASZ;
    __nv_bfloat16* Bh = Al + 2 * ASZ;                // [2][BSZ]
    __nv_bfloat16* Bl = Bh + 2 * BSZ;

    const int tid = threadIdx.x;
    const int m0 = blockIdx.x * 128;
    const int w = tid >> 5, lane = tid & 31;
    const int wm = (w >> 1) * 32, wn = (w & 1) * 96;

    float4 aR[4], bR[6];

    auto LDG = [&](int kt) {
#pragma unroll
        for (int i = 0; i < 4; ++i) {
            const int f = tid + 256 * i;
            const int row = f >> 3, kc = (f & 7) * 4;
            aR[i] = *(const float4*)&X[(size_t)(m0 + row) * 512 + kt + kc];
        }
#pragma unroll
        for (int i = 0; i < 6; ++i) {
            const int f = tid + 256 * i;
            const int k = f / 48, n4 = (f % 48) * 4;
            bR[i] = (n4 < N) ? *(const float4*)&W[(size_t)(kt + k) * N + n4]
                             : make_float4(0.f, 0.f, 0.f, 0.f);
        }
    };
    auto STS = [&](int buf) {
#pragma unroll
        for (int i = 0; i < 4; ++i) {
            const int f = tid + 256 * i;
            const int row = f >> 3, kc = (f & 7) * 4;
            __nv_bfloat16 h0, l0, h1, l1, h2, l2, h3, l3;
            split_bf16(aR[i].x, h0, l0); split_bf16(aR[i].y, h1, l1);
            split_bf16(aR[i].z, h2, l2); split_bf16(aR[i].w, h3, l3);
            *(ushort4*)&Ah[buf * ASZ + row * PA + kc] = make_ushort4(
                __bfloat16_as_ushort(h0), __bfloat16_as_ushort(h1),
                __bfloat16_as_ushort(h2), __bfloat16_as_ushort(h3));
            *(ushort4*)&Al[buf * ASZ + row * PA + kc] = make_ushort4(
                __bfloat16_as_ushort(l0), __bfloat16_as_ushort(l1),
                __bfloat16_as_ushort(l2), __bfloat16_as_ushort(l3));
        }
#pragma unroll
        for (int i = 0; i < 6; ++i) {
            const int f = tid + 256 * i;
            const int k = f / 48, n4 = (f % 48) * 4;
            __nv_bfloat16 h0, l0, h1, l1, h2, l2, h3, l3;
            split_bf16(bR[i].x, h0, l0); split_bf16(bR[i].y, h1, l1);
            split_bf16(bR[i].z, h2, l2); split_bf16(bR[i].w, h3, l3);
            *(ushort4*)&Bh[buf * BSZ + k * PB + n4] = make_ushort4(
                __bfloat16_as_ushort(h0), __bfloat16_as_ushort(h1),
                __bfloat16_as_ushort(h2), __bfloat16_as_ushort(h3));
            *(ushort4*)&Bl[buf * BSZ + k * PB + n4] = make_ushort4(
                __bfloat16_as_ushort(l0), __bfloat16_as_ushort(l1),
                __bfloat16_as_ushort(l2), __bfloat16_as_ushort(l3));
        }
    };

    float acc[2][12][4];
#pragma unroll
    for (int mt = 0; mt < 2; ++mt)
#pragma unroll
        for (int nt = 0; nt < 12; ++nt)
#pragma unroll
            for (int c = 0; c < 4; ++c) acc[mt][nt][c] = 0.f;

    LDG(0); STS(0);
    __syncthreads();

    for (int s = 0; s < 16; ++s) {
        const int cur = s & 1;
        if (s < 15) LDG((s + 1) * 32);
#pragma unroll
        for (int ks = 0; ks < 2; ++ks) {
            uint32_t ah[2][4], al[2][4];
#pragma unroll
            for (int mt = 0; mt < 2; ++mt) {
                const int ro = (wm + mt * 16 + (lane & 15)) * PA + ks * 16 + ((lane >> 4) & 1) * 8;
                ldsm_x4(sptr(&Ah[cur * ASZ + ro]), ah[mt][0], ah[mt][1], ah[mt][2], ah[mt][3]);
                ldsm_x4(sptr(&Al[cur * ASZ + ro]), al[mt][0], al[mt][1], al[mt][2], al[mt][3]);
            }
#pragma unroll
            for (int ntp = 0; ntp < 6; ++ntp) {
                uint32_t bh[4], bl[4];
                const int ro = (ks * 16 + (lane & 15)) * PB + wn + ntp * 16 + (lane >> 4) * 8;
                ldsm_x4_t(sptr(&Bh[cur * BSZ + ro]), bh[0], bh[1], bh[2], bh[3]);
                ldsm_x4_t(sptr(&Bl[cur * BSZ + ro]), bl[0], bl[1], bl[2], bl[3]);
#pragma unroll
                for (int sub = 0; sub < 2; ++sub) {
                    const int q = sub * 2;
#pragma unroll
                    for (int mt = 0; mt < 2; ++mt) {
                        float* a4 = acc[mt][ntp * 2 + sub];
                        mma_bf16(a4, al[mt], bh[q], bh[q + 1]);
                        mma_bf16(a4, ah[mt], bl[q], bl[q + 1]);
                        mma_bf16(a4, ah[mt], bh[q], bh[q + 1]);
                    }
                }
            }
        }
        if (s < 15) { STS(cur ^ 1); __syncthreads(); }
    }

    // ---- epilogue: bias add, then route to pre-split globals
#pragma unroll
    for (int mt = 0; mt < 2; ++mt) {
        const int r = m0 + wm + mt * 16 + (lane >> 2);   // rows r and r+8
#pragma unroll
        for (int nt = 0; nt < 12; ++nt) {
            const int col = wn + nt * 8 + (lane & 3) * 2;
            if (col >= N) continue;
            const float b0 = bias[col], b1 = bias[col + 1];
            const float v0 = acc[mt][nt][0] + b0, v1 = acc[mt][nt][1] + b1;
            const float v2 = acc[mt][nt][2] + b0, v3 = acc[mt][nt][3] + b1;
            const int t1 = r >> 6, bb1 = r & 63;
            const int t2 = (r + 8) >> 6, bb2 = (r + 8) & 63;
            if (col < 160) {
                const size_t i1 = ((size_t)(bb1 << 9) + t1) * 160 + col;
                const size_t i2 = ((size_t)(bb2 << 9) + t2) * 160 + col;
                if (mode == 0) {
                    *(ushort2*)&g_kh[i1] = pack_hi2(v0, v1);
                    *(ushort2*)&g_kl[i1] = pack_lo2(v0, v1);
                    *(ushort2*)&g_kh[i2] = pack_hi2(v2, v3);
                    *(ushort2*)&g_kl[i2] = pack_lo2(v2, v3);
                } else {
                    *(ushort2*)&g_qh[i1] = pack_hi2(v0, v1);
                    *(ushort2*)&g_ql[i1] = pack_lo2(v0, v1);
                    *(ushort2*)&g_qh[i2] = pack_hi2(v2, v3);
                    *(ushort2*)&g_ql[i2] = pack_lo2(v2, v3);
                }
            } else if (mode == 1) {   // p columns (fp32)
                *(float2*)&g_p[((size_t)(bb1 << 9) + t1) * 20 + col - 160] = make_float2(v0, v1);
                *(float2*)&g_p[((size_t)(bb2 << 9) + t2) * 20 + col - 160] = make_float2(v2, v3);
            }
        }
    }
}

// ---------------------------------------------------------------------------
// pe projection: (1023,192) @ (192,20) -> g_pe
// ---------------------------------------------------------------------------
__global__ __launch_bounds__(256)
void pe_proj_kernel(const float* __restrict__ pos, const float* __restrict__ Wp)
{
    const int idx = blockIdx.x * 256 + threadIdx.x;
    if (idx >= 1023 * 20) return;
    const int n = idx / 20;
    const int c = idx % 20;
    float s = 0.f;
#pragma unroll 8
    for (int d = 0; d < 192; ++d)
        s = fmaf(pos[n * 192 + d], Wp[d * 20 + c], s);
    g_pe[idx] = s;
}

// ---------------------------------------------------------------------------
// Attention weights via tensor cores.
// Block = (b, h, 32 t-rows x 512 keys). 8 warps = 8 col-strips of 64.
// Scores in registers (acc[2][8][4] = 64/thread). Pos/mask/softmax epilogue.
// ---------------------------------------------------------------------------
#define KPAD 40

__global__ __launch_bounds__(256, 2)
void attn_kernel(const unsigned char* __restrict__ mask, float* __restrict__ out)
{
    extern __shared__ char smem_raw[];
    __nv_bfloat16* Kh = (__nv_bfloat16*)smem_raw;       // [512][KPAD]
    __nv_bfloat16* Kl = Kh + 512 * KPAD;
    __nv_bfloat16* Qh = Kl + 512 * KPAD;                // [32][KPAD]
    __nv_bfloat16* Ql = Qh + 32 * KPAD;
    float4* pes = (float4*)(Ql + 32 * KPAD);            // [543]
    float4* ps  = pes + 543;                            // [32]
    unsigned char* msk = (unsigned char*)(ps + 32);     // [512]
    float* redm = (float*)(msk + 512);                  // [32][8]
    float* reds = redm + 256;                           // [32][8]

    const int t0 = blockIdx.x * 32;
    const int b  = blockIdx.y;
    const int h  = blockIdx.z;
    const int tid = threadIdx.x;

    // ---- loads: K (512x32 hi/lo), Q (32x32 hi/lo), pes, p, mask
    {
        const __nv_bfloat16* sh = g_kh + ((size_t)(b << 9)) * 160 + h * 32;
        const __nv_bfloat16* sl = g_kl + ((size_t)(b << 9)) * 160 + h * 32;
        for (int it = tid; it < 2048; it += 256) {
            const int j = it >> 2, c = it & 3;
            *(uint4*)&Kh[j * KPAD + c * 8] = *(const uint4*)(sh + (size_t)j * 160 + c * 8);
            *(uint4*)&Kl[j * KPAD + c * 8] = *(const uint4*)(sl + (size_t)j * 160 + c * 8);
        }
    }
    if (tid < 128) {
        const int j = tid >> 2, c = tid & 3;
        const size_t o = ((size_t)(b << 9) + t0 + j) * 160 + h * 32 + c * 8;
        *(uint4*)&Qh[j * KPAD + c * 8] = *(const uint4*)(g_qh + o);
        *(uint4*)&Ql[j * KPAD + c * 8] = *(const uint4*)(g_ql + o);
    }
    for (int it = tid; it < 543; it += 256)
        pes[it] = *(const float4*)&g_pe[(480 - t0 + it) * 20 + h * 4];
    if (tid >= 128 && tid < 160) {
        const int rl = tid - 128;
        ps[rl] = *(const float4*)&g_p[((size_t)(b << 9) + t0 + rl) * 20 + h * 4];
    }
    for (int it = tid; it < 512; it += 256) msk[it] = mask[b * 512 + it];
    __syncthreads();

    const int w = tid >> 5, lane = tid & 31;
    const int wn = w * 64;

    float acc[2][8][4];
#pragma unroll
    for (int mt = 0; mt < 2; ++mt)
#pragma unroll
        for (int nt = 0; nt < 8; ++nt)
#pragma unroll
            for (int c = 0; c < 4; ++c) acc[mt][nt][c] = 0.f;

    // ---- QK^T: 3-term split bf16 MMA, K=32 (2 k-steps)
#pragma unroll
    for (int ks = 0; ks < 2; ++ks) {
        uint32_t ah[2][4], al[2][4];
#pragma unroll
        for (int mt = 0; mt < 2; ++mt) {
            const int ro = (mt * 16 + (lane & 15)) * KPAD + ks * 16 + ((lane >> 4) & 1) * 8;
            ldsm_x4(sptr(&Qh[ro]), ah[mt][0], ah[mt][1], ah[mt][2], ah[mt][3]);
            ldsm_x4(sptr(&Ql[ro]), al[mt][0], al[mt][1], al[mt][2], al[mt][3]);
        }
#pragma unroll
        for (int ntp = 0; ntp < 4; ++ntp) {
            uint32_t bh[4], bl[4];
            const int ro = (wn + ntp * 16 + (lane & 7) + ((lane >> 4) & 1) * 8) * KPAD
                         + ks * 16 + ((lane >> 3) & 1) * 8;
            ldsm_x4(sptr(&Kh[ro]), bh[0], bh[1], bh[2], bh[3]);
            ldsm_x4(sptr(&Kl[ro]), bl[0], bl[1], bl[2], bl[3]);
#pragma unroll
            for (int sub = 0; sub < 2; ++sub) {
                const int q = sub * 2;
#pragma unroll
                for (int mt = 0; mt < 2; ++mt) {
                    float* a4 = acc[mt][ntp * 2 + sub];
                    mma_bf16(a4, al[mt], bh[q], bh[q + 1]);
                    mma_bf16(a4, ah[mt], bl[q], bl[q + 1]);
                    mma_bf16(a4, ah[mt], bh[q], bh[q + 1]);
                }
            }
        }
    }

    const int r0l = lane >> 2;            // row within 8-row group
    const int c0  = (lane & 3) * 2;       // col pair base

    // mask bytes for this thread's 16 columns
    unsigned char mb[16];
#pragma unroll
    for (int nt = 0; nt < 8; ++nt) {
        mb[nt * 2 + 0] = msk[wn + nt * 8 + c0 + 0];
        mb[nt * 2 + 1] = msk[wn + nt * 8 + c0 + 1];
    }

    // ---- positional scores + mask (rel-shift: idx = col - rl + 31)
#pragma unroll
    for (int mt = 0; mt < 2; ++mt)
#pragma unroll
        for (int cp = 0; cp < 2; ++cp) {
            const int rl = mt * 16 + cp * 8 + r0l;
            const float4 pv = ps[rl];
#pragma unroll
            for (int nt = 0; nt < 8; ++nt)
#pragma unroll
                for (int c = 0; c < 2; ++c) {
                    const int col = wn + nt * 8 + c0 + c;
                    const float4 ev = pes[col + 31 - rl];
                    float v = acc[mt][nt][cp * 2 + c]
                            + pv.x * ev.x + pv.y * ev.y + pv.z * ev.z + pv.w * ev.w;
                    acc[mt][nt][cp * 2 + c] = mb[nt * 2 + c] ? -1000.f : v;
                }
        }

    // ---- softmax (row = warp 64-col strip -> cross-warp combine via smem)
#pragma unroll
    for (int mt = 0; mt < 2; ++mt)
#pragma unroll
        for (int cp = 0; cp < 2; ++cp) {
            const int rl = mt * 16 + cp * 8 + r0l;
            float m = -3.4e38f;
#pragma unroll
            for (int nt = 0; nt < 8; ++nt) {
                m = fmaxf(m, acc[mt][nt][cp * 2 + 0]);
                m = fmaxf(m, acc[mt][nt][cp * 2 + 1]);
            }
            m = fmaxf(m, __shfl_xor_sync(0xffffffffu, m, 1));
            m = fmaxf(m, __shfl_xor_sync(0xffffffffu, m, 2));
            if ((lane & 3) == 0) redm[rl * 8 + w] = m;
        }
    __syncthreads();

    float inv[2][2];
#pragma unroll
    for (int mt = 0; mt < 2; ++mt)
#pragma unroll
        for (int cp = 0; cp < 2; ++cp) {
            const int rl = mt * 16 + cp * 8 + r0l;
            const float4 m0v = *(const float4*)&redm[rl * 8];
            const float4 m1v = *(const float4*)&redm[rl * 8 + 4];
            const float gm = fmaxf(fmaxf(fmaxf(m0v.x, m0v.y), fmaxf(m0v.z, m0v.w)),
                                   fmaxf(fmaxf(m1v.x, m1v.y), fmaxf(m1v.z, m1v.w)));
            float s = 0.f;
#pragma unroll
            for (int nt = 0; nt < 8; ++nt) {
                float e0 = __expf(acc[mt][nt][cp * 2 + 0] - gm);
                float e1 = __expf(acc[mt][nt][cp * 2 + 1] - gm);
                acc[mt][nt][cp * 2 + 0] = e0;
                acc[mt][nt][cp * 2 + 1] = e1;
                s += e0 + e1;
            }
            s += __shfl_xor_sync(0xffffffffu, s, 1);
            s += __shfl_xor_sync(0xffffffffu, s, 2);
            if ((lane & 3) == 0) reds[rl * 8 + w] = s;
        }
    __syncthreads();
#pragma unroll
    for (int mt = 0; mt < 2; ++mt)
#pragma unroll
        for (int cp = 0; cp < 2; ++cp) {
            const int rl = mt * 16 + cp * 8 + r0l;
            const float4 s0v = *(const float4*)&reds[rl * 8];
            const float4 s1v = *(const float4*)&reds[rl * 8 + 4];
            inv[mt][cp] = 1.f / (s0v.x + s0v.y + s0v.z + s0v.w +
                                 s1v.x + s1v.y + s1v.z + s1v.w);
        }

    // ---- write
#pragma unroll
    for (int mt = 0; mt < 2; ++mt)
#pragma unroll
        for (int cp = 0; cp < 2; ++cp) {
            const int rl = mt * 16 + cp * 8 + r0l;
            const size_t base = (((size_t)h * 64 + b) * 512 + t0 + rl) * 512;
            const float iv = inv[mt][cp];
#pragma unroll
            for (int nt = 0; nt < 8; ++nt) {
                float2 o;
                o.x = acc[mt][nt][cp * 2 + 0] * iv;
                o.y = acc[mt][nt][cp * 2 + 1] * iv;
                *(float2*)&out[base + wn + nt * 8 + c0] = o;
            }
        }
}

// ---------------------------------------------------------------------------
extern "C" void kernel_launch(void* const* d_in, const int* in_sizes, int n_in,
                              void* d_out, int out_size)
{
    const float* lm_pruned = (const float*)d_in[0];
    const float* am_pruned = (const float*)d_in[1];
    const float* pos_emb   = (const float*)d_in[2];
    const unsigned char* kpm = (const unsigned char*)d_in[3];
    const float* W_lm  = (const float*)d_in[4];
    const float* b_lm  = (const float*)d_in[5];
    const float* W_am  = (const float*)d_in[6];
    const float* b_am  = (const float*)d_in[7];
    const float* W_pos = (const float*)d_in[8];
    float* out = (float*)d_out;

    const int proj_smem = (2 * ASZ + 2 * BSZ) * 2 * 2;   // 92160 bytes
    static int inited = 0;
    cudaFuncSetAttribute(proj_mma2, cudaFuncAttributeMaxDynamicSharedMemorySize, proj_smem);

    proj_mma2<<<256, 256, proj_smem>>>(lm_pruned, W_lm, b_lm, 180, 1);
    proj_mma2<<<256, 256, proj_smem>>>(am_pruned, W_am, b_am, 160, 0);
    pe_proj_kernel<<<80, 256>>>(pos_emb, W_pos);

    const int attn_smem = (512 * KPAD + 32 * KPAD) * 2 * 2   // K,Q hi/lo bf16
                        + 543 * 16 + 32 * 16 + 512           // pes, ps, mask
                        + 2 * 256 * 4;                       // redm, reds
    cudaFuncSetAttribute(attn_kernel, cudaFuncAttributeMaxDynamicSharedMemorySize, attn_smem);
    attn_kernel<<<dim3(16, 64, 5), 256, attn_smem>>>(kpm, out);
    (void)inited;
}